// round 2
// baseline (speedup 1.0000x reference)
#include <cuda_runtime.h>
#include <math.h>

#define TT 512
#define BB 32
#define KD 1024
#define GD 4096

// Scratch: x_proj [T, B, 4C] = 256 MB, LSTM state double-buffered h (transposed [c][b]) + c.
__device__ float g_xproj[(size_t)TT * BB * GD];
__device__ float g_hbuf[2][KD * BB];   // [c][b] layout
__device__ float g_cbuf[KD * BB];      // [c][b] layout

// ---------------------------------------------------------------------------
// Kernel 1: broadcast h0/c0 into state buffers
// ---------------------------------------------------------------------------
__global__ void init_state_kernel(const float* __restrict__ h0,
                                  const float* __restrict__ c0) {
    int i = blockIdx.x * blockDim.x + threadIdx.x;   // 0 .. 32767
    int c = i >> 5;                                  // i = c*32 + b
    g_hbuf[0][i] = h0[c];
    g_cbuf[i]    = c0[c];
}

// ---------------------------------------------------------------------------
// Kernel 2: x_proj GEMM.  A = embs [M=16384, K=1024] row-major,
// W = w_ih [N=4096, K=1024] row-major.  C[m][n] = dot(A[m], W[n]) + bias[n].
// 128x128 tile, BK=8, 256 threads, 8x8 register microtile, reg prefetch.
// ---------------------------------------------------------------------------
__global__ void __launch_bounds__(256)
xproj_gemm_kernel(const float* __restrict__ A,
                  const float* __restrict__ W,
                  const float* __restrict__ b_ih,
                  const float* __restrict__ b_hh) {
    __shared__ float As[8][128];
    __shared__ float Ws[8][128];

    const int tid = threadIdx.x;
    const int bm  = blockIdx.y * 128;
    const int bn  = blockIdx.x * 128;
    const int row = tid >> 1;            // 0..127
    const int kof = (tid & 1) * 4;       // 0 or 4
    const int tx  = tid & 15;            // n direction
    const int ty  = tid >> 4;            // m direction

    const float* Aptr = A + (size_t)(bm + row) * KD + kof;
    const float* Wptr = W + (size_t)(bn + row) * KD + kof;

    float4 av = *(const float4*)Aptr;
    float4 wv = *(const float4*)Wptr;

    float acc[8][8];
#pragma unroll
    for (int i = 0; i < 8; i++)
#pragma unroll
        for (int j = 0; j < 8; j++) acc[i][j] = 0.f;

    for (int k0 = 0; k0 < KD; k0 += 8) {
        __syncthreads();
        As[kof + 0][row] = av.x; As[kof + 1][row] = av.y;
        As[kof + 2][row] = av.z; As[kof + 3][row] = av.w;
        Ws[kof + 0][row] = wv.x; Ws[kof + 1][row] = wv.y;
        Ws[kof + 2][row] = wv.z; Ws[kof + 3][row] = wv.w;
        __syncthreads();
        if (k0 + 8 < KD) {
            av = *(const float4*)(Aptr + k0 + 8);
            wv = *(const float4*)(Wptr + k0 + 8);
        }
#pragma unroll
        for (int k = 0; k < 8; k++) {
            float4 a0 = *(const float4*)&As[k][ty * 8];
            float4 a1 = *(const float4*)&As[k][ty * 8 + 4];
            float4 w0 = *(const float4*)&Ws[k][tx * 8];
            float4 w1 = *(const float4*)&Ws[k][tx * 8 + 4];
            float am[8] = {a0.x, a0.y, a0.z, a0.w, a1.x, a1.y, a1.z, a1.w};
            float wm[8] = {w0.x, w0.y, w0.z, w0.w, w1.x, w1.y, w1.z, w1.w};
#pragma unroll
            for (int i = 0; i < 8; i++)
#pragma unroll
                for (int j = 0; j < 8; j++) acc[i][j] += am[i] * wm[j];
        }
    }

    float bias[8];
#pragma unroll
    for (int j = 0; j < 8; j++) {
        int n = bn + tx * 8 + j;
        bias[j] = b_ih[n] + b_hh[n];
    }
#pragma unroll
    for (int i = 0; i < 8; i++) {
        size_t off = (size_t)(bm + ty * 8 + i) * GD + bn + tx * 8;
        float4 o0, o1;
        o0.x = acc[i][0] + bias[0]; o0.y = acc[i][1] + bias[1];
        o0.z = acc[i][2] + bias[2]; o0.w = acc[i][3] + bias[3];
        o1.x = acc[i][4] + bias[4]; o1.y = acc[i][5] + bias[5];
        o1.z = acc[i][6] + bias[6]; o1.w = acc[i][7] + bias[7];
        *(float4*)&g_xproj[off]     = o0;
        *(float4*)&g_xproj[off + 4] = o1;
    }
}

// ---------------------------------------------------------------------------
// Kernel 3: one LSTM timestep.
// Block = 32 g-rows x 32 b.  The 32 g-rows are the 4 gate rows (i,f,g,o) of
// 8 consecutive c-values, so each block can finish c/h elementwise locally.
// 128 blocks (c-tiles), 128 threads, rb=2 x rg=4 microtile, BK=32 panels with
// register prefetch.  h state is double-buffered ([c][b] transposed) so the
// epilogue write never races another block's mainloop reads.
// ---------------------------------------------------------------------------
__global__ void __launch_bounds__(128)
lstm_step_kernel(const float* __restrict__ w_hh,
                 float* __restrict__ out, int t) {
    __shared__ float h_s[32][32];   // [k][b]
    __shared__ float w_s[32][32];   // [k][r]

    const int tid    = threadIdx.x;
    const int c_base = blockIdx.x * 8;
    const int bx = tid & 15;        // b group
    const int gy = tid >> 4;        // 0..7 = local c
    // w loading: row r_l = gate*8 + c_local
    const int r_l = tid >> 2;       // 0..31
    const int qq  = tid & 3;        // 0..3
    const int gate_r = r_l >> 3;
    const int c_r    = c_base + (r_l & 7);
    const float* wrow = w_hh + (size_t)(gate_r * KD + c_r) * KD;

    const float* hin  = g_hbuf[t & 1];
    float*       hout = g_hbuf[(t & 1) ^ 1];

    float4 hv0 = *(const float4*)&hin[tid * 8];
    float4 hv1 = *(const float4*)&hin[tid * 8 + 4];
    float4 wv0 = *(const float4*)&wrow[qq * 4];
    float4 wv1 = *(const float4*)&wrow[16 + qq * 4];

    float acc[2][4];
#pragma unroll
    for (int i = 0; i < 2; i++)
#pragma unroll
        for (int j = 0; j < 4; j++) acc[i][j] = 0.f;

    for (int k0 = 0; k0 < KD; k0 += 32) {
        __syncthreads();
        *(float4*)((float*)h_s + tid * 8)     = hv0;
        *(float4*)((float*)h_s + tid * 8 + 4) = hv1;
        w_s[qq * 4 + 0][r_l] = wv0.x; w_s[qq * 4 + 1][r_l] = wv0.y;
        w_s[qq * 4 + 2][r_l] = wv0.z; w_s[qq * 4 + 3][r_l] = wv0.w;
        w_s[16 + qq * 4 + 0][r_l] = wv1.x; w_s[16 + qq * 4 + 1][r_l] = wv1.y;
        w_s[16 + qq * 4 + 2][r_l] = wv1.z; w_s[16 + qq * 4 + 3][r_l] = wv1.w;
        __syncthreads();
        if (k0 + 32 < KD) {
            hv0 = *(const float4*)&hin[(k0 + 32) * 32 + tid * 8];
            hv1 = *(const float4*)&hin[(k0 + 32) * 32 + tid * 8 + 4];
            wv0 = *(const float4*)&wrow[k0 + 32 + qq * 4];
            wv1 = *(const float4*)&wrow[k0 + 48 + qq * 4];
        }
#pragma unroll
        for (int k = 0; k < 32; k++) {
            float hb0 = h_s[k][bx];
            float hb1 = h_s[k][bx + 16];
            float w0 = w_s[k][gy];
            float w1 = w_s[k][gy + 8];
            float w2 = w_s[k][gy + 16];
            float w3 = w_s[k][gy + 24];
            acc[0][0] += hb0 * w0; acc[0][1] += hb0 * w1;
            acc[0][2] += hb0 * w2; acc[0][3] += hb0 * w3;
            acc[1][0] += hb1 * w0; acc[1][1] += hb1 * w1;
            acc[1][2] += hb1 * w2; acc[1][3] += hb1 * w3;
        }
    }

    const int c = c_base + gy;
#pragma unroll
    for (int i = 0; i < 2; i++) {
        int b = bx + i * 16;
        size_t xbase = ((size_t)t * BB + b) * GD + c;
        float gi = acc[i][0] + g_xproj[xbase];
        float gf = acc[i][1] + g_xproj[xbase + KD];
        float gg = acc[i][2] + g_xproj[xbase + 2 * KD];
        float go = acc[i][3] + g_xproj[xbase + 3 * KD];
        float ig = 1.f / (1.f + __expf(-gi));
        float fg = 1.f / (1.f + __expf(-gf));
        float gt = tanhf(gg);
        float og = 1.f / (1.f + __expf(-go));
        int sidx = c * BB + b;
        float cn = fg * g_cbuf[sidx] + ig * gt;
        float hn = og * tanhf(cn);
        g_cbuf[sidx] = cn;
        hout[sidx]   = hn;
        out[((size_t)t * BB + b) * KD + c] = hn;
    }
}

// ---------------------------------------------------------------------------
extern "C" void kernel_launch(void* const* d_in, const int* in_sizes, int n_in,
                              void* d_out, int out_size) {
    const float* embs = (const float*)d_in[0];
    const float* w_ih = (const float*)d_in[1];
    const float* w_hh = (const float*)d_in[2];
    const float* b_ih = (const float*)d_in[3];
    const float* b_hh = (const float*)d_in[4];
    const float* h0   = (const float*)d_in[5];
    const float* c0   = (const float*)d_in[6];
    float* out = (float*)d_out;

    init_state_kernel<<<128, 256>>>(h0, c0);

    dim3 g1(GD / 128, (TT * BB) / 128);   // (32, 128)
    xproj_gemm_kernel<<<g1, 256>>>(embs, w_ih, b_ih, b_hh);

    for (int t = 0; t < TT; t++) {
        lstm_step_kernel<<<128, 128>>>(w_hh, out, t);
    }
}

// round 3
// speedup vs baseline: 2.3573x; 2.3573x over previous
#include <cuda_runtime.h>
#include <math.h>

#define TT 512
#define BB 32
#define KD 1024
#define GD 4096
#define NBLK 128
#define NTHR 256

// Scratch (static __device__ allowed): x_proj [T,B,4C] = 256 MB,
// h state double-buffered transposed [c][b], barrier counter.
__device__ float g_xproj[(size_t)TT * BB * GD];
__device__ float g_hbuf[2][KD * BB];
__device__ unsigned g_bar_cnt;

// ---------------------------------------------------------------------------
// Kernel 1: broadcast h0 into h state, reset barrier
// ---------------------------------------------------------------------------
__global__ void init_state_kernel(const float* __restrict__ h0) {
    int i = blockIdx.x * blockDim.x + threadIdx.x;   // 0 .. 32767
    int c = i >> 5;
    g_hbuf[0][i] = h0[c];
    if (i == 0) g_bar_cnt = 0u;
}

// ---------------------------------------------------------------------------
// Kernel 2: x_proj GEMM (unchanged from R2; ~5.5 ms, next round's target)
// ---------------------------------------------------------------------------
__global__ void __launch_bounds__(256)
xproj_gemm_kernel(const float* __restrict__ A,
                  const float* __restrict__ W,
                  const float* __restrict__ b_ih,
                  const float* __restrict__ b_hh) {
    __shared__ float As[8][128];
    __shared__ float Ws[8][128];

    const int tid = threadIdx.x;
    const int bm  = blockIdx.y * 128;
    const int bn  = blockIdx.x * 128;
    const int row = tid >> 1;
    const int kof = (tid & 1) * 4;
    const int tx  = tid & 15;
    const int ty  = tid >> 4;

    const float* Aptr = A + (size_t)(bm + row) * KD + kof;
    const float* Wptr = W + (size_t)(bn + row) * KD + kof;

    float4 av = *(const float4*)Aptr;
    float4 wv = *(const float4*)Wptr;

    float acc[8][8];
#pragma unroll
    for (int i = 0; i < 8; i++)
#pragma unroll
        for (int j = 0; j < 8; j++) acc[i][j] = 0.f;

    for (int k0 = 0; k0 < KD; k0 += 8) {
        __syncthreads();
        As[kof + 0][row] = av.x; As[kof + 1][row] = av.y;
        As[kof + 2][row] = av.z; As[kof + 3][row] = av.w;
        Ws[kof + 0][row] = wv.x; Ws[kof + 1][row] = wv.y;
        Ws[kof + 2][row] = wv.z; Ws[kof + 3][row] = wv.w;
        __syncthreads();
        if (k0 + 8 < KD) {
            av = *(const float4*)(Aptr + k0 + 8);
            wv = *(const float4*)(Wptr + k0 + 8);
        }
#pragma unroll
        for (int k = 0; k < 8; k++) {
            float4 a0 = *(const float4*)&As[k][ty * 8];
            float4 a1 = *(const float4*)&As[k][ty * 8 + 4];
            float4 w0 = *(const float4*)&Ws[k][tx * 8];
            float4 w1 = *(const float4*)&Ws[k][tx * 8 + 4];
            float am[8] = {a0.x, a0.y, a0.z, a0.w, a1.x, a1.y, a1.z, a1.w};
            float wm[8] = {w0.x, w0.y, w0.z, w0.w, w1.x, w1.y, w1.z, w1.w};
#pragma unroll
            for (int i = 0; i < 8; i++)
#pragma unroll
                for (int j = 0; j < 8; j++) acc[i][j] += am[i] * wm[j];
        }
    }

    float bias[8];
#pragma unroll
    for (int j = 0; j < 8; j++) {
        int n = bn + tx * 8 + j;
        bias[j] = b_ih[n] + b_hh[n];
    }
#pragma unroll
    for (int i = 0; i < 8; i++) {
        size_t off = (size_t)(bm + ty * 8 + i) * GD + bn + tx * 8;
        float4 o0, o1;
        o0.x = acc[i][0] + bias[0]; o0.y = acc[i][1] + bias[1];
        o0.z = acc[i][2] + bias[2]; o0.w = acc[i][3] + bias[3];
        o1.x = acc[i][4] + bias[4]; o1.y = acc[i][5] + bias[5];
        o1.z = acc[i][6] + bias[6]; o1.w = acc[i][7] + bias[7];
        *(float4*)&g_xproj[off]     = o0;
        *(float4*)&g_xproj[off + 4] = o1;
    }
}

// ---------------------------------------------------------------------------
// Kernel 3: PERSISTENT recurrence kernel. 128 blocks x 256 threads, 1/SM.
// Block owns 32 w_hh rows (4 gates x 8 c) in SMEM for all 512 steps.
// Per step: 8 warps split K (128 each), microtile 4r x 8b, smem reduction,
// fused gate epilogue, register-resident c-state, atomic-counter barrier.
// ---------------------------------------------------------------------------
extern __shared__ float smem_dyn[];

__global__ void __launch_bounds__(NTHR, 1)
lstm_persistent_kernel(const float* __restrict__ w_hh,
                       const float* __restrict__ c0,
                       float* __restrict__ out) {
    float* w_s = smem_dyn;            // [1024][32] k-major, 128 KB
    float* hp  = smem_dyn + 32768;    // 8192 floats = 32 KB: staging + partials

    const int tid  = threadIdx.x;
    const int blk  = blockIdx.x;
    const int c_base = blk * 8;

    // ---- load w_hh slice transposed into smem: w_s[k*32 + r], r = gate*8+cl
    {
        const int r    = tid & 31;            // 0..31
        const int kg   = tid >> 5;            // 0..7
        const int gate = r >> 3;
        const int cl   = r & 7;
        const float* wrow = w_hh + (size_t)(gate * KD + c_base + cl) * KD;
#pragma unroll 8
        for (int kk = 0; kk < 128; kk++) {
            int k = kg * 128 + kk;
            w_s[k * 32 + r] = wrow[k];        // STS conflict-free (lanes r)
        }
    }

    // ---- FMA identities: warp = k-slice, lane -> (r_grp, b_grp)
    const int warp  = tid >> 5;
    const int lane  = tid & 31;
    const int r_grp = lane >> 2;              // rows r_grp*4 .. +3
    const int b_grp = lane & 3;               // b   b_grp*8 .. +7
    float* my_stage = hp + warp * 1024;       // 512-float staging buffer

    // ---- epilogue identities: warp = cl, lane = b
    const int eb  = lane;
    const int ecl = warp;
    const int ec  = c_base + ecl;
    float c_state = c0[ec];                   // register-resident for all T

    __syncthreads();

    for (int t = 0; t < TT; t++) {
        const float* hin  = g_hbuf[t & 1];
        float*       hout = g_hbuf[(t & 1) ^ 1];

        // prefetch this step's xproj gate values (hidden under k-loop)
        const float* xp = g_xproj + ((size_t)t * BB + eb) * GD + ec;
        float x_i = __ldg(xp);
        float x_f = __ldg(xp + KD);
        float x_g = __ldg(xp + 2 * KD);
        float x_o = __ldg(xp + 3 * KD);

        // prefetch h chunk 0 (L2, bypass incoherent L1)
        const float* hsrc = hin + warp * 128 * 32;
        float4 pf[4];
#pragma unroll
        for (int i = 0; i < 4; i++)
            pf[i] = __ldcg((const float4*)(hsrc + i * 128 + lane * 4));

        float acc[4][8];
#pragma unroll
        for (int ri = 0; ri < 4; ri++)
#pragma unroll
            for (int bi = 0; bi < 8; bi++) acc[ri][bi] = 0.f;

        for (int ch = 0; ch < 8; ch++) {
            // stage prefetched chunk into smem
#pragma unroll
            for (int i = 0; i < 4; i++)
                *(float4*)(my_stage + i * 128 + lane * 4) = pf[i];
            __syncwarp();
            // prefetch next chunk (overlaps compute)
            if (ch < 7) {
#pragma unroll
                for (int i = 0; i < 4; i++)
                    pf[i] = __ldcg((const float4*)(hsrc + (ch + 1) * 512 + i * 128 + lane * 4));
            }
            const float* wk = w_s + (warp * 128 + ch * 16) * 32;
#pragma unroll
            for (int kk = 0; kk < 16; kk++) {
                float4 h0 = *(const float4*)(my_stage + kk * 32 + b_grp * 8);
                float4 h1 = *(const float4*)(my_stage + kk * 32 + b_grp * 8 + 4);
                float4 wv = *(const float4*)(wk + kk * 32 + r_grp * 4);
                float hv[8] = {h0.x, h0.y, h0.z, h0.w, h1.x, h1.y, h1.z, h1.w};
                float wr[4] = {wv.x, wv.y, wv.z, wv.w};
#pragma unroll
                for (int ri = 0; ri < 4; ri++)
#pragma unroll
                    for (int bi = 0; bi < 8; bi++)
                        acc[ri][bi] += wr[ri] * hv[bi];
            }
            __syncwarp();
        }

        // ---- write per-warp partials: part[warp*1024 + r*32 + b]
        __syncthreads();
#pragma unroll
        for (int ri = 0; ri < 4; ri++) {
            int r = r_grp * 4 + ri;
            float4 p0 = make_float4(acc[ri][0], acc[ri][1], acc[ri][2], acc[ri][3]);
            float4 p1 = make_float4(acc[ri][4], acc[ri][5], acc[ri][6], acc[ri][7]);
            *(float4*)(hp + warp * 1024 + r * 32 + b_grp * 8)     = p0;
            *(float4*)(hp + warp * 1024 + r * 32 + b_grp * 8 + 4) = p1;
        }
        __syncthreads();

        // ---- reduce 8 partials + fused gates (thread = (cl, b))
        float gi = x_i, gf = x_f, gg = x_g, go = x_o;
#pragma unroll
        for (int j = 0; j < 8; j++) {
            const float* p = hp + j * 1024 + ecl * 32 + eb;
            gi += p[0 * 8 * 32];
            gf += p[1 * 8 * 32];
            gg += p[2 * 8 * 32];
            go += p[3 * 8 * 32];
        }
        float ig = 1.f / (1.f + __expf(-gi));
        float fg = 1.f / (1.f + __expf(-gf));
        float gt = tanhf(gg);
        float og = 1.f / (1.f + __expf(-go));
        c_state  = fg * c_state + ig * gt;
        float hn = og * tanhf(c_state);

        out[((size_t)t * BB + eb) * KD + ec] = hn;
        __stcg(&hout[ec * 32 + eb], hn);      // L2-visible for other SMs

        // ---- inter-block barrier (accumulating counter)
        if (t != TT - 1) {
            __threadfence();
            __syncthreads();
            if (tid == 0) {
                atomicAdd(&g_bar_cnt, 1u);
                unsigned target = (unsigned)(t + 1) * NBLK;
                while (*(volatile unsigned*)&g_bar_cnt < target) {
                    __nanosleep(64);
                }
            }
            __syncthreads();
            __threadfence();
        }
    }
}

// ---------------------------------------------------------------------------
extern "C" void kernel_launch(void* const* d_in, const int* in_sizes, int n_in,
                              void* d_out, int out_size) {
    const float* embs = (const float*)d_in[0];
    const float* w_ih = (const float*)d_in[1];
    const float* w_hh = (const float*)d_in[2];
    const float* b_ih = (const float*)d_in[3];
    const float* b_hh = (const float*)d_in[4];
    const float* h0   = (const float*)d_in[5];
    const float* c0   = (const float*)d_in[6];
    float* out = (float*)d_out;

    init_state_kernel<<<128, 256>>>(h0);

    dim3 g1(GD / 128, (TT * BB) / 128);
    xproj_gemm_kernel<<<g1, 256>>>(embs, w_ih, b_ih, b_hh);

    static int smem_set = 0;
    const int smem_bytes = (32768 + 8192) * (int)sizeof(float);  // 160 KB
    if (!smem_set) {
        cudaFuncSetAttribute(lstm_persistent_kernel,
                             cudaFuncAttributeMaxDynamicSharedMemorySize,
                             smem_bytes);
        smem_set = 1;
    }
    lstm_persistent_kernel<<<NBLK, NTHR, smem_bytes>>>(w_hh, c0, out);
}